// round 16
// baseline (speedup 1.0000x reference)
#include <cuda_runtime.h>
#include <cuda_bf16.h>
#include <cstdint>

// ---------------- problem constants ----------------
constexpr int D  = 128;
constexpr int NE = 500000;
constexpr int NG = 200000;
constexpr int NM = 40000;

constexpr int EB = (NE + 127) / 128;   // edge CTAs (TM=128)
constexpr int GB = (NG + 127) / 128;   // grid CTAs (TM=128)
constexpr int MB = (NM + 127) / 128;   // mesh CTAs (TM=128)

// weight image offsets (elements) into g_w_hi / g_w_lo (plain [K][128] row-major)
constexpr int OFF_EW1 = 0;                    // K=384
constexpr int OFF_EW2 = OFF_EW1 + 384 * 128;
constexpr int OFF_SW1 = OFF_EW2 + 128 * 128;
constexpr int OFF_SW2 = OFF_SW1 + 128 * 128;
constexpr int OFF_DW1 = OFF_SW2 + 128 * 128;  // K=256
constexpr int OFF_DW2 = OFF_DW1 + 256 * 128;
constexpr int W_TOT   = OFF_DW2 + 128 * 128;  // 147456

__device__ __align__(16) __nv_bfloat16 g_w_hi[W_TOT];
__device__ __align__(16) __nv_bfloat16 g_w_lo[W_TOT];
__device__ __align__(16) float g_agg[(size_t)NM * D];
__device__ int g_edge_done;

// ---------------- shared constants ----------------
constexpr int SB_STRIDE = 272;   // B bf16 row: 128 bf16 + 16B pad
constexpr int B_BUF     = 17408; // hi+lo per B buffer
constexpr int B_DELTA   = 8704;
constexpr int SA_STRIDE = 80;    // bf16 A row: 32 bf16 + 16B pad
constexpr int AF_STRIDE = 128;   // f32 staging row: 32 f32, no pad
constexpr int FB_STRIDE = 132;   // LN f32 buffer stride (elements)

// smem layout per tile size
template <int TMt> struct Lay {
    static constexpr int SRC     = 0;
    static constexpr int DST     = TMt * 4;
    static constexpr int PS      = 2 * TMt * 4;
    static constexpr int PQ      = PS + 1024;
    static constexpr int R       = PQ + 1024;           // overlay region
    static constexpr int AF_BUF  = TMt * AF_STRIDE;     // f32 staging buffer
    static constexpr int ABF     = R + 2 * AF_BUF;      // bf16 A buffers
    static constexpr int A_DELTA = TMt * SA_STRIDE;     // hi->lo
    static constexpr int ABF_BUF = 2 * A_DELTA;         // hi+lo per buffer
    static constexpr int H       = R;                   // H bf16 overlays staging+abf
    static constexpr int H_DELTA = TMt * SB_STRIDE;
    static constexpr int B       = R + TMt * 576;       // == ABF + 2*ABF_BUF
    static constexpr int SMEM    = B + 2 * B_BUF;
};
// TM=128: SMEM=111616 -> 2 CTAs/SM.

// ---------------- PTX helpers ----------------
__device__ __forceinline__ uint32_t smem_u32(const void* p) {
    uint32_t a;
    asm("{ .reg .u64 t; cvta.to.shared.u64 t, %1; cvt.u32.u64 %0, t; }" : "=r"(a) : "l"(p));
    return a;
}
__device__ __forceinline__ void ldmA(uint32_t a[4], uint32_t addr) {
    asm volatile("ldmatrix.sync.aligned.m8n8.x4.shared.b16 {%0,%1,%2,%3}, [%4];"
                 : "=r"(a[0]), "=r"(a[1]), "=r"(a[2]), "=r"(a[3]) : "r"(addr));
}
__device__ __forceinline__ void ldmBT(uint32_t b[2], uint32_t addr) {
    asm volatile("ldmatrix.sync.aligned.m8n8.x2.trans.shared.b16 {%0,%1}, [%2];"
                 : "=r"(b[0]), "=r"(b[1]) : "r"(addr));
}
__device__ __forceinline__ void mma16816(float c[4], const uint32_t a[4], const uint32_t b[2]) {
    asm volatile("mma.sync.aligned.m16n8k16.row.col.f32.bf16.bf16.f32 "
                 "{%0,%1,%2,%3}, {%4,%5,%6,%7}, {%8,%9}, {%0,%1,%2,%3};"
                 : "+f"(c[0]), "+f"(c[1]), "+f"(c[2]), "+f"(c[3])
                 : "r"(a[0]), "r"(a[1]), "r"(a[2]), "r"(a[3]), "r"(b[0]), "r"(b[1]));
}
__device__ __forceinline__ uint32_t pack_bf16(float lo, float hi) {
    uint32_t r;
    asm("cvt.rn.bf16x2.f32 %0, %1, %2;" : "=r"(r) : "f"(hi), "f"(lo));
    return r;
}
__device__ __forceinline__ void split2(float v, float& hf, float& lf) {
    __nv_bfloat16 h = __float2bfloat16(v);
    hf = __bfloat162float(h);
    lf = v - hf;
}
__device__ __forceinline__ void red_add4(float* p, float a, float b, float c, float d) {
    asm volatile("red.global.add.v4.f32 [%0], {%1,%2,%3,%4};"
                 :: "l"(p), "f"(a), "f"(b), "f"(c), "f"(d) : "memory");
}
__device__ __forceinline__ void cp16(uint32_t dst, const void* src) {
    asm volatile("cp.async.cg.shared.global [%0], [%1], 16;" :: "r"(dst), "l"(src));
}
#define CP_COMMIT() asm volatile("cp.async.commit_group;" ::: "memory")
#define CP_WAIT0()  asm volatile("cp.async.wait_group 0;" ::: "memory")

// ---------------- prep kernels ----------------
__global__ void prep_weights(const float* __restrict__ ew1, const float* __restrict__ ew2,
                             const float* __restrict__ sw1, const float* __restrict__ sw2,
                             const float* __restrict__ dw1, const float* __restrict__ dw2) {
    int i = blockIdx.x * blockDim.x + threadIdx.x;
    if (i >= W_TOT) return;
    const float* src; int base;
    if      (i < OFF_EW2) { src = ew1; base = OFF_EW1; }
    else if (i < OFF_SW1) { src = ew2; base = OFF_EW2; }
    else if (i < OFF_SW2) { src = sw1; base = OFF_SW1; }
    else if (i < OFF_DW1) { src = sw2; base = OFF_SW2; }
    else if (i < OFF_DW2) { src = dw1; base = OFF_DW1; }
    else                  { src = dw2; base = OFF_DW2; }
    float v = src[i - base];
    float hf, lf; split2(v, hf, lf);
    g_w_hi[i] = __float2bfloat16(hf);
    g_w_lo[i] = __float2bfloat16(lf);
}
__global__ void clear_agg_kernel() {
    int i = blockIdx.x * blockDim.x + threadIdx.x;
    if (i == 0) g_edge_done = 0;           // reset dependency counter every launch
    if (i < NM * D / 4) ((float4*)g_agg)[i] = make_float4(0.f, 0.f, 0.f, 0.f);
}

// ---------------- A gather source ----------------
template <int MODE>
__device__ __forceinline__ const float* srcA(const float* __restrict__ in0,
                                             const float* __restrict__ gf,
                                             const float* __restrict__ mf,
                                             const int* srcs, const int* dsts,
                                             int row, int r, int c4) {
    if (MODE == 0) {
        if (c4 < 32) return in0 + (size_t)row * D + c4 * 4;
        if (c4 < 64) return gf + (size_t)srcs[r] * D + (c4 - 32) * 4;
        return mf + (size_t)dsts[r] * D + (c4 - 64) * 4;
    } else if (MODE == 2) {
        if (c4 < 32) return g_agg + (size_t)row * D + c4 * 4;
        return in0 + (size_t)row * D + (c4 - 32) * 4;
    }
    return in0 + (size_t)row * D + c4 * 4;
}

template <int TMt, int MODE>
__device__ __forceinline__ void stage_A(uint32_t sb, int abuf,
                                        const float* __restrict__ in0,
                                        const float* __restrict__ gf,
                                        const float* __restrict__ mf,
                                        const int* srcs, const int* dsts,
                                        int row0, int nrows, int ch, int tid) {
#pragma unroll
    for (int u = 0; u < TMt / 32; ++u) {
        int t = tid + u * 256;
        int r = t >> 3, q = t & 7;
        int row = row0 + r;
        if (row >= nrows) row = nrows - 1;   // clamp; results discarded at output
        cp16(sb + abuf + r * AF_STRIDE + q * 16,
             srcA<MODE>(in0, gf, mf, srcs, dsts, row, r, ch * 8 + q));
    }
}

// convert staged f32 chunk -> bf16 hi/lo A buffer
template <int TMt>
__device__ __forceinline__ void convert_A(char* smem, int afbuf, int abf, int tid) {
#pragma unroll
    for (int u = 0; u < TMt / 32; ++u) {
        int t = tid + u * 256;
        int r = t >> 3, q = t & 7;
        float4 v = *(const float4*)(smem + afbuf + r * AF_STRIDE + q * 16);
        float h0, l0, h1, l1, h2, l2, h3, l3;
        split2(v.x, h0, l0); split2(v.y, h1, l1);
        split2(v.z, h2, l2); split2(v.w, h3, l3);
        *(uint2*)(smem + abf + r * SA_STRIDE + q * 8) =
            make_uint2(pack_bf16(h0, h1), pack_bf16(h2, h3));
        *(uint2*)(smem + abf + Lay<TMt>::A_DELTA + r * SA_STRIDE + q * 8) =
            make_uint2(pack_bf16(l0, l1), pack_bf16(l2, l3));
    }
}

// stage one 32-K weight chunk into a B buffer via cp.async (no commit)
__device__ __forceinline__ void stage_B(uint32_t sb, int bbuf, int woff, int ch, int tid) {
    const __nv_bfloat16* wh = g_w_hi + woff + ch * 32 * 128;
    const __nv_bfloat16* wl = g_w_lo + woff + ch * 32 * 128;
    for (int t = tid; t < 512; t += 256) {
        int r = t >> 4, q = t & 15;
        cp16(sb + bbuf + r * SB_STRIDE + q * 16, wh + r * 128 + q * 8);
        cp16(sb + bbuf + B_DELTA + r * SB_STRIDE + q * 16, wl + r * 128 + q * 8);
    }
}

// one 32-K chunk of split-bf16 MMAs; warp tile (16*NI) rows x 64 cols
template <int NI>
__device__ __forceinline__ void mma_chunk(uint32_t abase, uint32_t adelta, int astride,
                                          int kbyte0, uint32_t bbase,
                                          float acc[NI][8][4], int wr, int wc, int lane) {
#pragma unroll
    for (int k16 = 0; k16 < 2; ++k16) {
        uint32_t ah[NI][4], al[NI][4];
#pragma unroll
        for (int i = 0; i < NI; ++i) {
            uint32_t ad = abase + (wr * (16 * NI) + i * 16 + (lane & 15)) * astride
                        + kbyte0 + k16 * 32 + (lane >> 4) * 16;
            ldmA(ah[i], ad);
            ldmA(al[i], ad + adelta);
        }
#pragma unroll
        for (int j = 0; j < 8; ++j) {
            uint32_t bh[2], bl[2];
            uint32_t bd = bbase + (k16 * 16 + (lane & 15)) * SB_STRIDE + (wc * 64 + j * 8) * 2;
            ldmBT(bh, bd);
            ldmBT(bl, bd + B_DELTA);
#pragma unroll
            for (int i = 0; i < NI; ++i) {
                mma16816(acc[i][j], ah[i], bh);
                mma16816(acc[i][j], ah[i], bl);
                mma16816(acc[i][j], al[i], bh);
            }
        }
    }
}

// ---------------- fused MLP body (explicit block id) ----------------
template <int TMt, int K1, int MODE>
__device__ __forceinline__ void mlp_body(char* smem, int bid,
    const float* __restrict__ in0, const float* __restrict__ gf, const float* __restrict__ mf,
    const int* __restrict__ src_idx, const int* __restrict__ dst_idx,
    int w1off, int w2off,
    const float* __restrict__ b1, const float* __restrict__ b2,
    const float* __restrict__ gam, const float* __restrict__ bet,
    float* __restrict__ out, int nrows)
{
    using L = Lay<TMt>;
    constexpr int NI = TMt / 64;
    constexpr int NC1 = K1 / 32;
    const uint32_t sb = smem_u32(smem);
    const int tid = threadIdx.x, wid = tid >> 5, lane = tid & 31;
    const int wr = wid & 3, wc = wid >> 2;
    const int gid = lane >> 2, tq = lane & 3;
    const int row0 = bid * TMt;

    int* srcs = (int*)(smem + L::SRC);
    int* dsts = (int*)(smem + L::DST);
    if (MODE == 0) {
        if (tid < TMt) {
            int e = row0 + tid;
            srcs[tid] = (e < nrows) ? src_idx[e] : 0;
            dsts[tid] = (e < nrows) ? dst_idx[e] : 0;
        }
        __syncthreads();
    }

    float acc[NI][8][4];
#pragma unroll
    for (int i = 0; i < NI; ++i)
#pragma unroll
        for (int j = 0; j < 8; ++j)
#pragma unroll
            for (int q = 0; q < 4; ++q) acc[i][j][q] = 0.f;

    // ===== GEMM1: single barrier per chunk; convert hidden behind MMA =====
    stage_A<TMt, MODE>(sb, L::R, in0, gf, mf, srcs, dsts, row0, nrows, 0, tid);
    stage_B(sb, L::B, w1off, 0, tid);
    CP_COMMIT();
    CP_WAIT0();
    __syncthreads();
    convert_A<TMt>(smem, L::R, L::ABF, tid);

    for (int ch = 0; ch < NC1; ++ch) {
        __syncthreads();   // convert(ch) + B[ch] published; mma(ch-1) done everywhere
        if (ch + 1 < NC1) {
            stage_A<TMt, MODE>(sb, L::R + ((ch + 1) & 1) * L::AF_BUF,
                               in0, gf, mf, srcs, dsts, row0, nrows, ch + 1, tid);
            stage_B(sb, L::B + ((ch + 1) & 1) * B_BUF, w1off, ch + 1, tid);
            CP_COMMIT();
        }
        mma_chunk<NI>(sb + L::ABF + (ch & 1) * L::ABF_BUF, L::A_DELTA, SA_STRIDE, 0,
                      sb + L::B + (ch & 1) * B_BUF, acc, wr, wc, lane);
        if (ch + 1 < NC1) {
            CP_WAIT0();
            convert_A<TMt>(smem, L::R + ((ch + 1) & 1) * L::AF_BUF,
                           L::ABF + ((ch + 1) & 1) * L::ABF_BUF, tid);
        }
    }
    __syncthreads();                   // GEMM1 done; staging/abf overlay -> H safe; B buf0 free
    stage_B(sb, L::B, w2off, 0, tid);  // prefetch W2[0] under epilogue1 (NC1 even -> buf0 free)
    CP_COMMIT();

    // ===== epilogue1: bias + SiLU -> H bf16 hi/lo =====
#pragma unroll
    for (int i = 0; i < NI; ++i) {
        int ra = wr * (16 * NI) + i * 16 + gid;
#pragma unroll
        for (int j = 0; j < 8; ++j) {
            int col = wc * 64 + j * 8 + tq * 2;
            float bb0 = __ldg(b1 + col), bb1 = __ldg(b1 + col + 1);
            float y0 = acc[i][j][0] + bb0, y1 = acc[i][j][1] + bb1;
            float y2 = acc[i][j][2] + bb0, y3 = acc[i][j][3] + bb1;
            y0 = y0 / (1.f + __expf(-y0)); y1 = y1 / (1.f + __expf(-y1));
            y2 = y2 / (1.f + __expf(-y2)); y3 = y3 / (1.f + __expf(-y3));
            float h0, l0, h1, l1, h2, l2, h3, l3;
            split2(y0, h0, l0); split2(y1, h1, l1);
            split2(y2, h2, l2); split2(y3, h3, l3);
            *(uint32_t*)(smem + L::H + ra * SB_STRIDE + col * 2)                  = pack_bf16(h0, h1);
            *(uint32_t*)(smem + L::H + L::H_DELTA + ra * SB_STRIDE + col * 2)     = pack_bf16(l0, l1);
            *(uint32_t*)(smem + L::H + (ra + 8) * SB_STRIDE + col * 2)            = pack_bf16(h2, h3);
            *(uint32_t*)(smem + L::H + L::H_DELTA + (ra + 8) * SB_STRIDE + col * 2) = pack_bf16(l2, l3);
        }
    }
#pragma unroll
    for (int i = 0; i < NI; ++i)
#pragma unroll
        for (int j = 0; j < 8; ++j)
#pragma unroll
            for (int q = 0; q < 4; ++q) acc[i][j][q] = 0.f;
    CP_WAIT0();   // W2[0] landed (hidden under epilogue1)

    // ===== GEMM2: H resident; B pipelined; one barrier per chunk =====
    for (int ch = 0; ch < 4; ++ch) {
        __syncthreads();   // H (ch0) / B[ch] published; mma(ch-1) done
        if (ch + 1 < 4) {
            stage_B(sb, L::B + ((ch + 1) & 1) * B_BUF, w2off, ch + 1, tid);
            CP_COMMIT();
        }
        mma_chunk<NI>(sb + L::H, L::H_DELTA, SB_STRIDE, ch * 64,
                      sb + L::B + (ch & 1) * B_BUF, acc, wr, wc, lane);
        if (ch + 1 < 4) CP_WAIT0();
    }

    // ===== epilogue2: bias + LayerNorm + output =====
    __syncthreads();   // all H reads done -> overlay f32 fbuf
    float* fbuf = (float*)(smem + L::R);
#pragma unroll
    for (int i = 0; i < NI; ++i) {
        int ra = wr * (16 * NI) + i * 16 + gid;
#pragma unroll
        for (int j = 0; j < 8; ++j) {
            int col = wc * 64 + j * 8 + tq * 2;
            float bb0 = __ldg(b2 + col), bb1 = __ldg(b2 + col + 1);
            fbuf[ra * FB_STRIDE + col]           = acc[i][j][0] + bb0;
            fbuf[ra * FB_STRIDE + col + 1]       = acc[i][j][1] + bb1;
            fbuf[(ra + 8) * FB_STRIDE + col]     = acc[i][j][2] + bb0;
            fbuf[(ra + 8) * FB_STRIDE + col + 1] = acc[i][j][3] + bb1;
        }
    }
    __syncthreads();
    {
        constexpr int PSH = (TMt == 128) ? 1 : 2;     // threads per row = 2 or 4
        constexpr int P   = 1 << PSH;
        constexpr int W   = 128 / P;                  // cols per thread
        const int row = tid >> PSH, part = tid & (P - 1);
        const int cb = part * W;
        const float* rp = fbuf + row * FB_STRIDE + cb;
        float s = 0.f, ssq = 0.f;
#pragma unroll
        for (int q = 0; q < W / 4; ++q) {
            float4 y4 = ((const float4*)rp)[q];
            s   += y4.x + y4.y + y4.z + y4.w;
            ssq += y4.x * y4.x + y4.y * y4.y + y4.z * y4.z + y4.w * y4.w;
        }
        float* psum = (float*)(smem + L::PS);
        float* pssq = (float*)(smem + L::PQ);
        psum[row * P + part] = s;
        pssq[row * P + part] = ssq;
        __syncthreads();
        float st = 0.f, sst = 0.f;
#pragma unroll
        for (int p = 0; p < P; ++p) { st += psum[row * P + p]; sst += pssq[row * P + p]; }
        float mu   = st * (1.f / 128.f);
        float var  = sst * (1.f / 128.f) - mu * mu;
        float rstd = rsqrtf(var + 1e-5f);
        int grow = row0 + row;
        if (grow < nrows) {
            if (MODE == 0) {
                float* bp = g_agg + (size_t)dsts[row] * D + cb;
#pragma unroll
                for (int q = 0; q < W / 4; ++q) {
                    float4 y4 = ((const float4*)rp)[q];
                    int c = cb + q * 4;
                    float o0 = (y4.x - mu) * rstd * __ldg(gam + c)     + __ldg(bet + c);
                    float o1 = (y4.y - mu) * rstd * __ldg(gam + c + 1) + __ldg(bet + c + 1);
                    float o2 = (y4.z - mu) * rstd * __ldg(gam + c + 2) + __ldg(bet + c + 2);
                    float o3 = (y4.w - mu) * rstd * __ldg(gam + c + 3) + __ldg(bet + c + 3);
                    red_add4(bp + q * 4, o0, o1, o2, o3);
                }
            } else {
                const float4* rsp = (const float4*)(in0 + (size_t)grow * D + cb);
                float4*       op  = (float4*)(out + (size_t)grow * D + cb);
#pragma unroll
                for (int q = 0; q < W / 4; ++q) {
                    float4 y4 = ((const float4*)rp)[q];
                    float4 r4 = rsp[q];
                    int c = cb + q * 4;
                    op[q] = make_float4(
                        (y4.x - mu) * rstd * __ldg(gam + c)     + __ldg(bet + c)     + r4.x,
                        (y4.y - mu) * rstd * __ldg(gam + c + 1) + __ldg(bet + c + 1) + r4.y,
                        (y4.z - mu) * rstd * __ldg(gam + c + 2) + __ldg(bet + c + 2) + r4.z,
                        (y4.w - mu) * rstd * __ldg(gam + c + 3) + __ldg(bet + c + 3) + r4.w);
                }
            }
        }
    }
    if (MODE == 0) {
        // signal: all this CTA's red.v4 scatters are visible device-wide
        __threadfence();
        __syncthreads();
        if (tid == 0) atomicAdd(&g_edge_done, 1);
    }
}

// ---------------- single merged kernel: edge -> grid -> mesh ----------------
// blocks [0,EB) edge, [EB,EB+GB) grid, [EB+GB,EB+GB+MB) mesh (spins on g_edge_done)
__global__ __launch_bounds__(256, 2) void k_all(
    const float* g2m, const float* gf, const float* mf,
    const int* si, const int* di,
    const float* eb1, const float* eb2, const float* eg, const float* ebt,
    const float* sb1, const float* sb2, const float* sg, const float* sbt,
    const float* db1, const float* db2, const float* dg, const float* dbt,
    float* out_grid, float* out_mesh) {
    extern __shared__ char smem[];
    if (blockIdx.x < EB) {
        mlp_body<128, 384, 0>(smem, blockIdx.x, g2m, gf, mf, si, di,
                              OFF_EW1, OFF_EW2, eb1, eb2, eg, ebt, nullptr, NE);
    } else if (blockIdx.x < EB + GB) {
        mlp_body<128, 128, 1>(smem, blockIdx.x - EB, gf, nullptr, nullptr, nullptr, nullptr,
                              OFF_SW1, OFF_SW2, sb1, sb2, sg, sbt, out_grid, NG);
    } else {
        // wait for all edge CTAs' scatters (issued in-order before us -> always completes)
        if (threadIdx.x == 0) {
            while (*(volatile int*)&g_edge_done < EB) __nanosleep(100);
        }
        __syncthreads();
        __threadfence();
        mlp_body<128, 256, 2>(smem, blockIdx.x - EB - GB, mf, nullptr, nullptr, nullptr, nullptr,
                              OFF_DW1, OFF_DW2, db1, db2, dg, dbt, out_mesh, NM);
    }
}

// ---------------- launch ----------------
extern "C" void kernel_launch(void* const* d_in, const int* in_sizes, int n_in,
                              void* d_out, int out_size) {
    const float* g2m   = (const float*)d_in[0];
    const float* gfeat = (const float*)d_in[1];
    const float* mfeat = (const float*)d_in[2];
    const int*   src   = (const int*)d_in[3];
    const int*   dst   = (const int*)d_in[4];
    const float* ew1 = (const float*)d_in[5],  *eb1 = (const float*)d_in[6];
    const float* ew2 = (const float*)d_in[7],  *eb2 = (const float*)d_in[8];
    const float* eg  = (const float*)d_in[9],  *ebt = (const float*)d_in[10];
    const float* sw1 = (const float*)d_in[11], *sb1 = (const float*)d_in[12];
    const float* sw2 = (const float*)d_in[13], *sb2 = (const float*)d_in[14];
    const float* sg  = (const float*)d_in[15], *sbt = (const float*)d_in[16];
    const float* dw1 = (const float*)d_in[17], *db1 = (const float*)d_in[18];
    const float* dw2 = (const float*)d_in[19], *db2 = (const float*)d_in[20];
    const float* dg  = (const float*)d_in[21], *dbt = (const float*)d_in[22];

    float* out_grid = (float*)d_out;
    float* out_mesh = out_grid + (size_t)NG * D;

    static int attr_done = 0;
    if (!attr_done) {
        cudaFuncSetAttribute(k_all, cudaFuncAttributeMaxDynamicSharedMemorySize, Lay<128>::SMEM);
        attr_done = 1;
    }

    prep_weights<<<(W_TOT + 255) / 256, 256>>>(ew1, ew2, sw1, sw2, dw1, dw2);
    clear_agg_kernel<<<(NM * D / 4 + 255) / 256, 256>>>();

    k_all<<<EB + GB + MB, 256, Lay<128>::SMEM>>>(
        g2m, gfeat, mfeat, src, dst,
        eb1, eb2, eg, ebt,
        sb1, sb2, sg, sbt,
        db1, db2, dg, dbt,
        out_grid, out_mesh);
}

// round 17
// speedup vs baseline: 1.0290x; 1.0290x over previous
#include <cuda_runtime.h>
#include <cuda_bf16.h>
#include <cstdint>

// ---------------- problem constants ----------------
constexpr int D  = 128;
constexpr int NE = 500000;
constexpr int NG = 200000;
constexpr int NM = 40000;

constexpr int EB  = (NE + 127) / 128;   // edge CTAs (TM=128)
constexpr int GB  = (NG + 127) / 128;   // grid CTAs (TM=128)
constexpr int PGB = (NG + 127) / 128;   // proj-grid CTAs
constexpr int PMB = (NM + 127) / 128;   // proj-mesh CTAs

// weight image offsets (elements) into g_w_hi / g_w_lo (plain [K][128] row-major)
constexpr int OFF_EW1 = 0;                    // K=384
constexpr int OFF_EW2 = OFF_EW1 + 384 * 128;
constexpr int OFF_SW1 = OFF_EW2 + 128 * 128;
constexpr int OFF_SW2 = OFF_SW1 + 128 * 128;
constexpr int OFF_DW1 = OFF_SW2 + 128 * 128;  // K=256
constexpr int OFF_DW2 = OFF_DW1 + 256 * 128;
constexpr int W_TOT   = OFF_DW2 + 128 * 128;  // 147456

__device__ __align__(16) __nv_bfloat16 g_w_hi[W_TOT];
__device__ __align__(16) __nv_bfloat16 g_w_lo[W_TOT];
__device__ __align__(16) float g_agg[(size_t)NM * D];
__device__ __align__(16) float g_pg[(size_t)NG * D];   // grid_feat @ W1[128:256]
__device__ __align__(16) float g_pm[(size_t)NM * D];   // mesh_feat @ W1[256:384]

// ---------------- shared constants ----------------
constexpr int SB_STRIDE = 272;   // B bf16 row: 128 bf16 + 16B pad
constexpr int B_BUF     = 17408; // hi+lo per B buffer
constexpr int B_DELTA   = 8704;
constexpr int SA_STRIDE = 80;    // bf16 A row: 32 bf16 + 16B pad
constexpr int AF_STRIDE = 128;   // f32 staging row: 32 f32, no pad
constexpr int FB_STRIDE = 132;   // LN f32 buffer stride (elements)

// smem layout per tile size
template <int TMt> struct Lay {
    static constexpr int SRC     = 0;
    static constexpr int DST     = TMt * 4;
    static constexpr int PS      = 2 * TMt * 4;
    static constexpr int PQ      = PS + 1024;
    static constexpr int R       = PQ + 1024;           // overlay region
    static constexpr int AF_BUF  = TMt * AF_STRIDE;     // f32 staging buffer
    static constexpr int ABF     = R + 2 * AF_BUF;      // bf16 A buffers
    static constexpr int A_DELTA = TMt * SA_STRIDE;     // hi->lo
    static constexpr int ABF_BUF = 2 * A_DELTA;         // hi+lo per buffer
    static constexpr int H       = R;                   // H bf16 overlays staging+abf
    static constexpr int H_DELTA = TMt * SB_STRIDE;
    static constexpr int B       = R + TMt * 576;       // == ABF + 2*ABF_BUF
    static constexpr int SMEM    = B + 2 * B_BUF;
};
// TM=128: SMEM=111616 -> 2 CTAs/SM.  TM=64: SMEM=74240 -> 3 CTAs/SM.

// ---------------- PTX helpers ----------------
__device__ __forceinline__ uint32_t smem_u32(const void* p) {
    uint32_t a;
    asm("{ .reg .u64 t; cvta.to.shared.u64 t, %1; cvt.u32.u64 %0, t; }" : "=r"(a) : "l"(p));
    return a;
}
__device__ __forceinline__ void ldmA(uint32_t a[4], uint32_t addr) {
    asm volatile("ldmatrix.sync.aligned.m8n8.x4.shared.b16 {%0,%1,%2,%3}, [%4];"
                 : "=r"(a[0]), "=r"(a[1]), "=r"(a[2]), "=r"(a[3]) : "r"(addr));
}
__device__ __forceinline__ void ldmBT(uint32_t b[2], uint32_t addr) {
    asm volatile("ldmatrix.sync.aligned.m8n8.x2.trans.shared.b16 {%0,%1}, [%2];"
                 : "=r"(b[0]), "=r"(b[1]) : "r"(addr));
}
__device__ __forceinline__ void mma16816(float c[4], const uint32_t a[4], const uint32_t b[2]) {
    asm volatile("mma.sync.aligned.m16n8k16.row.col.f32.bf16.bf16.f32 "
                 "{%0,%1,%2,%3}, {%4,%5,%6,%7}, {%8,%9}, {%0,%1,%2,%3};"
                 : "+f"(c[0]), "+f"(c[1]), "+f"(c[2]), "+f"(c[3])
                 : "r"(a[0]), "r"(a[1]), "r"(a[2]), "r"(a[3]), "r"(b[0]), "r"(b[1]));
}
__device__ __forceinline__ uint32_t pack_bf16(float lo, float hi) {
    uint32_t r;
    asm("cvt.rn.bf16x2.f32 %0, %1, %2;" : "=r"(r) : "f"(hi), "f"(lo));
    return r;
}
__device__ __forceinline__ void split2(float v, float& hf, float& lf) {
    __nv_bfloat16 h = __float2bfloat16(v);
    hf = __bfloat162float(h);
    lf = v - hf;
}
__device__ __forceinline__ void red_add4(float* p, float a, float b, float c, float d) {
    asm volatile("red.global.add.v4.f32 [%0], {%1,%2,%3,%4};"
                 :: "l"(p), "f"(a), "f"(b), "f"(c), "f"(d) : "memory");
}
__device__ __forceinline__ void cp16(uint32_t dst, const void* src) {
    asm volatile("cp.async.cg.shared.global [%0], [%1], 16;" :: "r"(dst), "l"(src));
}
#define CP_COMMIT() asm volatile("cp.async.commit_group;" ::: "memory")
#define CP_WAIT0()  asm volatile("cp.async.wait_group 0;" ::: "memory")

// ---------------- prep kernels ----------------
__global__ void prep_weights(const float* __restrict__ ew1, const float* __restrict__ ew2,
                             const float* __restrict__ sw1, const float* __restrict__ sw2,
                             const float* __restrict__ dw1, const float* __restrict__ dw2) {
    int i = blockIdx.x * blockDim.x + threadIdx.x;
    if (i >= W_TOT) return;
    const float* src; int base;
    if      (i < OFF_EW2) { src = ew1; base = OFF_EW1; }
    else if (i < OFF_SW1) { src = ew2; base = OFF_EW2; }
    else if (i < OFF_SW2) { src = sw1; base = OFF_SW1; }
    else if (i < OFF_DW1) { src = sw2; base = OFF_SW2; }
    else if (i < OFF_DW2) { src = dw1; base = OFF_DW1; }
    else                  { src = dw2; base = OFF_DW2; }
    float v = src[i - base];
    float hf, lf; split2(v, hf, lf);
    g_w_hi[i] = __float2bfloat16(hf);
    g_w_lo[i] = __float2bfloat16(lf);
}
__global__ void clear_agg_kernel() {
    int i = blockIdx.x * blockDim.x + threadIdx.x;
    if (i < NM * D / 4) ((float4*)g_agg)[i] = make_float4(0.f, 0.f, 0.f, 0.f);
}

// ---------------- A gather source ----------------
// MODE 0: edge (g2m rows only — node parts precomputed)  MODE 1: plain rows  MODE 2: [g_agg, mesh]
template <int MODE>
__device__ __forceinline__ const float* srcA(const float* __restrict__ in0,
                                             int row, int c4) {
    if (MODE == 2) {
        if (c4 < 32) return g_agg + (size_t)row * D + c4 * 4;
        return in0 + (size_t)row * D + (c4 - 32) * 4;
    }
    return in0 + (size_t)row * D + c4 * 4;
}

template <int TMt, int MODE>
__device__ __forceinline__ void stage_A(uint32_t sb, int abuf,
                                        const float* __restrict__ in0,
                                        int row0, int nrows, int ch, int tid) {
#pragma unroll
    for (int u = 0; u < TMt / 32; ++u) {
        int t = tid + u * 256;
        int r = t >> 3, q = t & 7;
        int row = row0 + r;
        if (row >= nrows) row = nrows - 1;   // clamp; results discarded at output
        cp16(sb + abuf + r * AF_STRIDE + q * 16, srcA<MODE>(in0, row, ch * 8 + q));
    }
}

// convert staged f32 chunk -> bf16 hi/lo A buffer
template <int TMt>
__device__ __forceinline__ void convert_A(char* smem, int afbuf, int abf, int tid) {
#pragma unroll
    for (int u = 0; u < TMt / 32; ++u) {
        int t = tid + u * 256;
        int r = t >> 3, q = t & 7;
        float4 v = *(const float4*)(smem + afbuf + r * AF_STRIDE + q * 16);
        float h0, l0, h1, l1, h2, l2, h3, l3;
        split2(v.x, h0, l0); split2(v.y, h1, l1);
        split2(v.z, h2, l2); split2(v.w, h3, l3);
        *(uint2*)(smem + abf + r * SA_STRIDE + q * 8) =
            make_uint2(pack_bf16(h0, h1), pack_bf16(h2, h3));
        *(uint2*)(smem + abf + Lay<TMt>::A_DELTA + r * SA_STRIDE + q * 8) =
            make_uint2(pack_bf16(l0, l1), pack_bf16(l2, l3));
    }
}

// stage one 32-K weight chunk into a B buffer via cp.async (no commit)
__device__ __forceinline__ void stage_B(uint32_t sb, int bbuf, int woff, int ch, int tid) {
    const __nv_bfloat16* wh = g_w_hi + woff + ch * 32 * 128;
    const __nv_bfloat16* wl = g_w_lo + woff + ch * 32 * 128;
    for (int t = tid; t < 512; t += 256) {
        int r = t >> 4, q = t & 15;
        cp16(sb + bbuf + r * SB_STRIDE + q * 16, wh + r * 128 + q * 8);
        cp16(sb + bbuf + B_DELTA + r * SB_STRIDE + q * 16, wl + r * 128 + q * 8);
    }
}

// one 32-K chunk of split-bf16 MMAs; warp tile (16*NI) rows x 64 cols
template <int NI>
__device__ __forceinline__ void mma_chunk(uint32_t abase, uint32_t adelta, int astride,
                                          int kbyte0, uint32_t bbase,
                                          float acc[NI][8][4], int wr, int wc, int lane) {
#pragma unroll
    for (int k16 = 0; k16 < 2; ++k16) {
        uint32_t ah[NI][4], al[NI][4];
#pragma unroll
        for (int i = 0; i < NI; ++i) {
            uint32_t ad = abase + (wr * (16 * NI) + i * 16 + (lane & 15)) * astride
                        + kbyte0 + k16 * 32 + (lane >> 4) * 16;
            ldmA(ah[i], ad);
            ldmA(al[i], ad + adelta);
        }
#pragma unroll
        for (int j = 0; j < 8; ++j) {
            uint32_t bh[2], bl[2];
            uint32_t bd = bbase + (k16 * 16 + (lane & 15)) * SB_STRIDE + (wc * 64 + j * 8) * 2;
            ldmBT(bh, bd);
            ldmBT(bl, bd + B_DELTA);
#pragma unroll
            for (int i = 0; i < NI; ++i) {
                mma16816(acc[i][j], ah[i], bh);
                mma16816(acc[i][j], ah[i], bl);
                mma16816(acc[i][j], al[i], bh);
            }
        }
    }
}

// shared GEMM1 pipeline (stage A+B, convert, mma over NC1 chunks)
template <int TMt, int MODE, int NC1, int NI>
__device__ __forceinline__ void gemm1_loop(char* smem, uint32_t sb,
                                           const float* __restrict__ in0,
                                           int w1off, int row0, int nrows, int tid,
                                           float acc[NI][8][4], int wr, int wc, int lane) {
    using L = Lay<TMt>;
    stage_A<TMt, MODE>(sb, L::R, in0, row0, nrows, 0, tid);
    stage_B(sb, L::B, w1off, 0, tid);
    CP_COMMIT();
    CP_WAIT0();
    __syncthreads();
    convert_A<TMt>(smem, L::R, L::ABF, tid);

    for (int ch = 0; ch < NC1; ++ch) {
        __syncthreads();   // convert(ch) + B[ch] published; mma(ch-1) done everywhere
        if (ch + 1 < NC1) {
            stage_A<TMt, MODE>(sb, L::R + ((ch + 1) & 1) * L::AF_BUF, in0, row0, nrows, ch + 1, tid);
            stage_B(sb, L::B + ((ch + 1) & 1) * B_BUF, w1off, ch + 1, tid);
            CP_COMMIT();
        }
        mma_chunk<NI>(sb + L::ABF + (ch & 1) * L::ABF_BUF, L::A_DELTA, SA_STRIDE, 0,
                      sb + L::B + (ch & 1) * B_BUF, acc, wr, wc, lane);
        if (ch + 1 < NC1) {
            CP_WAIT0();
            convert_A<TMt>(smem, L::R + ((ch + 1) & 1) * L::AF_BUF,
                           L::ABF + ((ch + 1) & 1) * L::ABF_BUF, tid);
        }
    }
}

// ---------------- projection body: out[row] = in0[row] @ W (raw f32, no bias) ----------------
__device__ __forceinline__ void proj_body(char* smem, int bid,
    const float* __restrict__ in0, int w1off, float* __restrict__ out, int nrows)
{
    constexpr int TMt = 128;
    using L = Lay<TMt>;
    constexpr int NI = 2;
    const uint32_t sb = smem_u32(smem);
    const int tid = threadIdx.x, wid = tid >> 5, lane = tid & 31;
    const int wr = wid & 3, wc = wid >> 2;
    const int gid = lane >> 2, tq = lane & 3;
    const int row0 = bid * TMt;

    float acc[NI][8][4];
#pragma unroll
    for (int i = 0; i < NI; ++i)
#pragma unroll
        for (int j = 0; j < 8; ++j)
#pragma unroll
            for (int q = 0; q < 4; ++q) acc[i][j][q] = 0.f;

    gemm1_loop<TMt, 1, 4, NI>(smem, sb, in0, w1off, row0, nrows, tid, acc, wr, wc, lane);

    __syncthreads();   // mma done -> overlay f32 fbuf
    float* fbuf = (float*)(smem + L::R);
#pragma unroll
    for (int i = 0; i < NI; ++i) {
        int ra = wr * 32 + i * 16 + gid;
#pragma unroll
        for (int j = 0; j < 8; ++j) {
            int col = wc * 64 + j * 8 + tq * 2;
            fbuf[ra * FB_STRIDE + col]           = acc[i][j][0];
            fbuf[ra * FB_STRIDE + col + 1]       = acc[i][j][1];
            fbuf[(ra + 8) * FB_STRIDE + col]     = acc[i][j][2];
            fbuf[(ra + 8) * FB_STRIDE + col + 1] = acc[i][j][3];
        }
    }
    __syncthreads();
    {
        const int row = tid >> 1, half = tid & 1;
        const int cb = half * 64;
        int grow = row0 + row;
        if (grow < nrows) {
            const float* rp = fbuf + row * FB_STRIDE + cb;
            float4* op = (float4*)(out + (size_t)grow * D + cb);
#pragma unroll
            for (int q = 0; q < 16; ++q) op[q] = ((const float4*)rp)[q];
        }
    }
}

// ---------------- fused MLP body ----------------
// MODE 0: edge (K1=128 g2m GEMM + Pg[src]+Pm[dst] in epilogue, LN, red.v4 scatter)
// MODE 1: grid  MODE 2: mesh
template <int TMt, int K1, int MODE>
__device__ __forceinline__ void mlp_body(char* smem, int bid,
    const float* __restrict__ in0,
    const int* __restrict__ src_idx, const int* __restrict__ dst_idx,
    int w1off, int w2off,
    const float* __restrict__ b1, const float* __restrict__ b2,
    const float* __restrict__ gam, const float* __restrict__ bet,
    float* __restrict__ out, int nrows)
{
    using L = Lay<TMt>;
    constexpr int NI = TMt / 64;
    constexpr int NC1 = K1 / 32;
    const uint32_t sb = smem_u32(smem);
    const int tid = threadIdx.x, wid = tid >> 5, lane = tid & 31;
    const int wr = wid & 3, wc = wid >> 2;
    const int gid = lane >> 2, tq = lane & 3;
    const int row0 = bid * TMt;

    int* srcs = (int*)(smem + L::SRC);
    int* dsts = (int*)(smem + L::DST);
    if (MODE == 0) {
        if (tid < TMt) {
            int e = row0 + tid;
            srcs[tid] = (e < nrows) ? src_idx[e] : 0;
            dsts[tid] = (e < nrows) ? dst_idx[e] : 0;
        }
        __syncthreads();
    }

    float acc[NI][8][4];
#pragma unroll
    for (int i = 0; i < NI; ++i)
#pragma unroll
        for (int j = 0; j < 8; ++j)
#pragma unroll
            for (int q = 0; q < 4; ++q) acc[i][j][q] = 0.f;

    gemm1_loop<TMt, MODE, NC1, NI>(smem, sb, in0, w1off, row0, nrows, tid, acc, wr, wc, lane);

    __syncthreads();                   // GEMM1 done; staging/abf overlay -> H safe; B buf0 free
    stage_B(sb, L::B, w2off, 0, tid);  // prefetch W2[0] under epilogue1 (NC1 even -> buf0 free)
    CP_COMMIT();

    // ===== epilogue1: bias (+ P gather for edge) + SiLU -> H bf16 hi/lo =====
#pragma unroll
    for (int i = 0; i < NI; ++i) {
        int ra = wr * (16 * NI) + i * 16 + gid;
        const float *pga, *pma, *pgb, *pmb;
        if (MODE == 0) {
            pga = g_pg + (size_t)srcs[ra] * D;
            pma = g_pm + (size_t)dsts[ra] * D;
            pgb = g_pg + (size_t)srcs[ra + 8] * D;
            pmb = g_pm + (size_t)dsts[ra + 8] * D;
        }
#pragma unroll
        for (int j = 0; j < 8; ++j) {
            int col = wc * 64 + j * 8 + tq * 2;
            float bb0 = __ldg(b1 + col), bb1 = __ldg(b1 + col + 1);
            float y0 = acc[i][j][0] + bb0, y1 = acc[i][j][1] + bb1;
            float y2 = acc[i][j][2] + bb0, y3 = acc[i][j][3] + bb1;
            if (MODE == 0) {
                float2 ga = *(const float2*)(pga + col), ma = *(const float2*)(pma + col);
                float2 gb = *(const float2*)(pgb + col), mb = *(const float2*)(pmb + col);
                y0 += ga.x + ma.x; y1 += ga.y + ma.y;
                y2 += gb.x + mb.x; y3 += gb.y + mb.y;
            }
            y0 = y0 / (1.f + __expf(-y0)); y1 = y1 / (1.f + __expf(-y1));
            y2 = y2 / (1.f + __expf(-y2)); y3 = y3 / (1.f + __expf(-y3));
            float h0, l0, h1, l1, h2, l2, h3, l3;
            split2(y0, h0, l0); split2(y1, h1, l1);
            split2(y2, h2, l2); split2(y3, h3, l3);
            *(uint32_t*)(smem + L::H + ra * SB_STRIDE + col * 2)                  = pack_bf16(h0, h1);
            *(uint32_t*)(smem + L::H + L::H_DELTA + ra * SB_STRIDE + col * 2)     = pack_bf16(l0, l1);
            *(uint32_t*)(smem + L::H + (ra + 8) * SB_STRIDE + col * 2)            = pack_bf16(h2, h3);
            *(uint32_t*)(smem + L::H + L::H_DELTA + (ra + 8) * SB_STRIDE + col * 2) = pack_bf16(l2, l3);
        }
    }
#pragma unroll
    for (int i = 0; i < NI; ++i)
#pragma unroll
        for (int j = 0; j < 8; ++j)
#pragma unroll
            for (int q = 0; q < 4; ++q) acc[i][j][q] = 0.f;
    CP_WAIT0();   // W2[0] landed (hidden under epilogue1)

    // ===== GEMM2: H resident; B pipelined; one barrier per chunk =====
    for (int ch = 0; ch < 4; ++ch) {
        __syncthreads();   // H (ch0) / B[ch] published; mma(ch-1) done
        if (ch + 1 < 4) {
            stage_B(sb, L::B + ((ch + 1) & 1) * B_BUF, w2off, ch + 1, tid);
            CP_COMMIT();
        }
        mma_chunk<NI>(sb + L::H, L::H_DELTA, SB_STRIDE, ch * 64,
                      sb + L::B + (ch & 1) * B_BUF, acc, wr, wc, lane);
        if (ch + 1 < 4) CP_WAIT0();
    }

    // ===== epilogue2: bias + LayerNorm + output =====
    __syncthreads();   // all H reads done -> overlay f32 fbuf
    float* fbuf = (float*)(smem + L::R);
#pragma unroll
    for (int i = 0; i < NI; ++i) {
        int ra = wr * (16 * NI) + i * 16 + gid;
#pragma unroll
        for (int j = 0; j < 8; ++j) {
            int col = wc * 64 + j * 8 + tq * 2;
            float bb0 = __ldg(b2 + col), bb1 = __ldg(b2 + col + 1);
            fbuf[ra * FB_STRIDE + col]           = acc[i][j][0] + bb0;
            fbuf[ra * FB_STRIDE + col + 1]       = acc[i][j][1] + bb1;
            fbuf[(ra + 8) * FB_STRIDE + col]     = acc[i][j][2] + bb0;
            fbuf[(ra + 8) * FB_STRIDE + col + 1] = acc[i][j][3] + bb1;
        }
    }
    __syncthreads();
    {
        constexpr int PSH = (TMt == 128) ? 1 : 2;     // threads per row = 2 or 4
        constexpr int P   = 1 << PSH;
        constexpr int W   = 128 / P;                  // cols per thread
        const int row = tid >> PSH, part = tid & (P - 1);
        const int cb = part * W;
        const float* rp = fbuf + row * FB_STRIDE + cb;
        float s = 0.f, ssq = 0.f;
#pragma unroll
        for (int q = 0; q < W / 4; ++q) {
            float4 y4 = ((const float4*)rp)[q];
            s   += y4.x + y4.y + y4.z + y4.w;
            ssq += y4.x * y4.x + y4.y * y4.y + y4.z * y4.z + y4.w * y4.w;
        }
        float* psum = (float*)(smem + L::PS);
        float* pssq = (float*)(smem + L::PQ);
        psum[row * P + part] = s;
        pssq[row * P + part] = ssq;
        __syncthreads();
        float st = 0.f, sst = 0.f;
#pragma unroll
        for (int p = 0; p < P; ++p) { st += psum[row * P + p]; sst += pssq[row * P + p]; }
        float mu   = st * (1.f / 128.f);
        float var  = sst * (1.f / 128.f) - mu * mu;
        float rstd = rsqrtf(var + 1e-5f);
        int grow = row0 + row;
        if (grow < nrows) {
            if (MODE == 0) {
                float* bp = g_agg + (size_t)dsts[row] * D + cb;
#pragma unroll
                for (int q = 0; q < W / 4; ++q) {
                    float4 y4 = ((const float4*)rp)[q];
                    int c = cb + q * 4;
                    float o0 = (y4.x - mu) * rstd * __ldg(gam + c)     + __ldg(bet + c);
                    float o1 = (y4.y - mu) * rstd * __ldg(gam + c + 1) + __ldg(bet + c + 1);
                    float o2 = (y4.z - mu) * rstd * __ldg(gam + c + 2) + __ldg(bet + c + 2);
                    float o3 = (y4.w - mu) * rstd * __ldg(gam + c + 3) + __ldg(bet + c + 3);
                    red_add4(bp + q * 4, o0, o1, o2, o3);
                }
            } else {
                const float4* rsp = (const float4*)(in0 + (size_t)grow * D + cb);
                float4*       op  = (float4*)(out + (size_t)grow * D + cb);
#pragma unroll
                for (int q = 0; q < W / 4; ++q) {
                    float4 y4 = ((const float4*)rp)[q];
                    float4 r4 = rsp[q];
                    int c = cb + q * 4;
                    op[q] = make_float4(
                        (y4.x - mu) * rstd * __ldg(gam + c)     + __ldg(bet + c)     + r4.x,
                        (y4.y - mu) * rstd * __ldg(gam + c + 1) + __ldg(bet + c + 1) + r4.y,
                        (y4.z - mu) * rstd * __ldg(gam + c + 2) + __ldg(bet + c + 2) + r4.z,
                        (y4.w - mu) * rstd * __ldg(gam + c + 3) + __ldg(bet + c + 3) + r4.w);
                }
            }
        }
    }
}

// ---------------- kernel wrappers ----------------
// projections: blocks [0,PGB) grid proj, [PGB,PGB+PMB) mesh proj
__global__ __launch_bounds__(256, 2) void k_proj(const float* gf, const float* mf) {
    extern __shared__ char smem[];
    if (blockIdx.x < PGB)
        proj_body(smem, blockIdx.x, gf, OFF_EW1 + 128 * 128, g_pg, NG);
    else
        proj_body(smem, blockIdx.x - PGB, mf, OFF_EW1 + 256 * 128, g_pm, NM);
}
// merged edge+grid: blocks [0,EB) edge (K1=128 now), [EB,EB+GB) grid
__global__ __launch_bounds__(256, 2) void k_edgegrid(
    const float* g2m, const float* gf,
    const int* si, const int* di,
    const float* eb1, const float* eb2, const float* eg, const float* ebt,
    const float* sb1, const float* sb2, const float* sg, const float* sbt,
    float* out_grid) {
    extern __shared__ char smem[];
    if (blockIdx.x < EB) {
        mlp_body<128, 128, 0>(smem, blockIdx.x, g2m, si, di,
                              OFF_EW1, OFF_EW2, eb1, eb2, eg, ebt, nullptr, NE);
    } else {
        mlp_body<128, 128, 1>(smem, blockIdx.x - EB, gf, nullptr, nullptr,
                              OFF_SW1, OFF_SW2, sb1, sb2, sg, sbt, out_grid, NG);
    }
}
__global__ __launch_bounds__(256, 3) void k_mesh(
    const float* in0,
    const float* b1, const float* b2, const float* g, const float* b,
    float* out, int n) {
    extern __shared__ char smem[];
    mlp_body<64, 256, 2>(smem, blockIdx.x, in0, nullptr, nullptr,
                         OFF_DW1, OFF_DW2, b1, b2, g, b, out, n);
}

// ---------------- launch ----------------
extern "C" void kernel_launch(void* const* d_in, const int* in_sizes, int n_in,
                              void* d_out, int out_size) {
    const float* g2m   = (const float*)d_in[0];
    const float* gfeat = (const float*)d_in[1];
    const float* mfeat = (const float*)d_in[2];
    const int*   src   = (const int*)d_in[3];
    const int*   dst   = (const int*)d_in[4];
    const float* ew1 = (const float*)d_in[5],  *eb1 = (const float*)d_in[6];
    const float* ew2 = (const float*)d_in[7],  *eb2 = (const float*)d_in[8];
    const float* eg  = (const float*)d_in[9],  *ebt = (const float*)d_in[10];
    const float* sw1 = (const float*)d_in[11], *sb1 = (const float*)d_in[12];
    const float* sw2 = (const float*)d_in[13], *sb2 = (const float*)d_in[14];
    const float* sg  = (const float*)d_in[15], *sbt = (const float*)d_in[16];
    const float* dw1 = (const float*)d_in[17], *db1 = (const float*)d_in[18];
    const float* dw2 = (const float*)d_in[19], *db2 = (const float*)d_in[20];
    const float* dg  = (const float*)d_in[21], *dbt = (const float*)d_in[22];

    float* out_grid = (float*)d_out;
    float* out_mesh = out_grid + (size_t)NG * D;

    static int attr_done = 0;
    if (!attr_done) {
        cudaFuncSetAttribute(k_proj,     cudaFuncAttributeMaxDynamicSharedMemorySize, Lay<128>::SMEM);
        cudaFuncSetAttribute(k_edgegrid, cudaFuncAttributeMaxDynamicSharedMemorySize, Lay<128>::SMEM);
        cudaFuncSetAttribute(k_mesh,     cudaFuncAttributeMaxDynamicSharedMemorySize, Lay<64>::SMEM);
        attr_done = 1;
    }

    prep_weights<<<(W_TOT + 255) / 256, 256>>>(ew1, ew2, sw1, sw2, dw1, dw2);
    clear_agg_kernel<<<(NM * D / 4 + 255) / 256, 256>>>();

    k_proj<<<PGB + PMB, 256, Lay<128>::SMEM>>>(gfeat, mfeat);

    k_edgegrid<<<EB + GB, 256, Lay<128>::SMEM>>>(
        g2m, gfeat, src, dst,
        eb1, eb2, eg, ebt,
        sb1, sb2, sg, sbt,
        out_grid);

    k_mesh<<<(NM + 63) / 64, 256, Lay<64>::SMEM>>>(
        mfeat, db1, db2, dg, dbt, out_mesh, NM);
}